// round 5
// baseline (speedup 1.0000x reference)
#include <cuda_runtime.h>
#include <math.h>

#define TT 512
#define BB 32
#define II 512
#define HH 1024
#define BH (BB*HH)
#define TBH (TT*BB*HH)
#define NBLK 128

__device__ float g_P[(size_t)4 * TBH];
__device__ float g_h[BH];
__device__ float g_c[2][BH];
__device__ float g_po[BH];
__device__ float g_acc[6 * 1024 * 32];
__device__ float g_bias[4][HH];
__device__ float g_Wpk[(size_t)7 * 64 * 16384];   // recurrent weights, frag-packed
__device__ float g_WpkI[(size_t)4 * 64 * 8192];   // input weights, frag-packed
__device__ unsigned g_cntM;
__device__ volatile unsigned g_genM;
__device__ unsigned g_cnt3;
__device__ volatile unsigned g_gen3;

__device__ __forceinline__ unsigned cvt_tf32(float x) {
    unsigned r; asm("cvt.rna.tf32.f32 %0, %1;" : "=r"(r) : "f"(x)); return r;
}
__device__ __forceinline__ void st4tf(float* p, float4 v) {
    uint4 u; u.x = cvt_tf32(v.x); u.y = cvt_tf32(v.y);
    u.z = cvt_tf32(v.z); u.w = cvt_tf32(v.w); *(uint4*)p = u;
}
__device__ __forceinline__ void mma_tf32(float* d, uint4 a, unsigned b0, unsigned b1) {
    asm("mma.sync.aligned.m16n8k8.row.col.f32.tf32.tf32.f32 "
        "{%0,%1,%2,%3},{%4,%5,%6,%7},{%8,%9},{%0,%1,%2,%3};"
        : "+f"(d[0]), "+f"(d[1]), "+f"(d[2]), "+f"(d[3])
        : "r"(a.x), "r"(a.y), "r"(a.z), "r"(a.w), "r"(b0), "r"(b1));
}
__device__ __forceinline__ void gbarM(unsigned target) {
    __syncthreads();
    if (threadIdx.x == 0) {
        __threadfence();
        unsigned old = atomicAdd(&g_cntM, 1);
        if (old == NBLK - 1) { g_cntM = 0; __threadfence(); g_genM = target; }
        else { while (g_genM < target) { } __threadfence(); }
    }
    __syncthreads();
}
__device__ __forceinline__ void gbar3(unsigned target) {
    __syncthreads();
    if (threadIdx.x == 0) {
        __threadfence();
        unsigned old = atomicAdd(&g_cnt3, 1);
        if (old == 86 - 1) { g_cnt3 = 0; __threadfence(); g_gen3 = target; }
        else { while (g_gen3 < target) { } __threadfence(); }
    }
    __syncthreads();
}

__global__ void __launch_bounds__(256) init_kernel(
    const float* __restrict__ h0, const float* __restrict__ c0,
    const float* __restrict__ b_ii, const float* __restrict__ b_hi,
    const float* __restrict__ b_ci, const float* __restrict__ b_if,
    const float* __restrict__ b_hf, const float* __restrict__ b_cf,
    const float* __restrict__ b_ic, const float* __restrict__ b_hc,
    const float* __restrict__ b_io, const float* __restrict__ b_ho,
    const float* __restrict__ b_cyo)
{
    int i = blockIdx.x * blockDim.x + threadIdx.x;
    if (i < BH) { g_h[i] = h0[i]; g_c[0][i] = c0[i]; }
    if (i < HH) {
        g_bias[0][i] = b_ii[i] + b_hi[i] + b_ci[i];
        g_bias[1][i] = b_if[i] + b_hf[i] + b_cf[i];
        g_bias[2][i] = b_ic[i] + b_hc[i];
        g_bias[3][i] = b_io[i] + b_ho[i] + b_cyo[i];
    }
    if (i == 0) { g_cntM = 0; g_genM = 0; g_cnt3 = 0; g_gen3 = 0; }
}

// pack 7 recurrent HxH matrices: [tile=mat*64+ng][kt 0..127][lane][jj]
__global__ void __launch_bounds__(256) pack_kernel(
    const float* __restrict__ w0, const float* __restrict__ w1,
    const float* __restrict__ w2, const float* __restrict__ w3,
    const float* __restrict__ w4, const float* __restrict__ w5,
    const float* __restrict__ w6)
{
    int gid = blockIdx.x * 256 + threadIdx.x;
    int mat = gid >> 20, rem = gid & 1048575;
    int ng = rem >> 14, kt = (rem >> 7) & 127, lane = (rem >> 2) & 31, jj = rem & 3;
    int row = ng * 16 + (lane >> 2) + 8 * (jj & 1);
    int col = kt * 8 + (lane & 3) + 4 * (jj >> 1);
    const float* W = (mat == 0) ? w0 : (mat == 1) ? w1 : (mat == 2) ? w2 :
                     (mat == 3) ? w3 : (mat == 4) ? w4 : (mat == 5) ? w5 : w6;
    g_Wpk[gid] = __uint_as_float(cvt_tf32(__ldg(&W[row * HH + col])));
}

// pack 4 input HxI matrices: [tile=mat*64+ng][kt 0..63][lane][jj]
__global__ void __launch_bounds__(256) pack_in_kernel(
    const float* __restrict__ w0, const float* __restrict__ w1,
    const float* __restrict__ w2, const float* __restrict__ w3)
{
    int gid = blockIdx.x * 256 + threadIdx.x;
    int mat = gid >> 19, rem = gid & 524287;
    int ng = rem >> 13, kt = (rem >> 7) & 63, lane = (rem >> 2) & 31, jj = rem & 3;
    int row = ng * 16 + (lane >> 2) + 8 * (jj & 1);
    int col = kt * 8 + (lane & 3) + 4 * (jj >> 1);
    const float* W = (mat == 0) ? w0 : (mat == 1) ? w1 : (mat == 2) ? w2 : w3;
    g_WpkI[gid] = __uint_as_float(cvt_tf32(__ldg(&W[row * II + col])));
}

// proj (tf32 mma): P[g][m][n] = X @ Wg^T + bias
// grid 128: bn = blk & 63 (64 n-rows), bm = blk >> 6 (8192 m each).
#define PROJ_SMEM (32768 + 2*2176 + 2176 + 64)
__global__ void __launch_bounds__(256) proj2_kernel(const float* __restrict__ X)
{
    extern __shared__ float smem[];
    float* sA = smem;                  // 4 tiles x 8192
    float* sX = smem + 32768;          // 2 x 2176
    float* sT = smem + 32768 + 4352;   // 2176
    float* sBias = sT + 2176;          // 64

    const int tid = threadIdx.x;
    const int bn = blockIdx.x & 63, bm = blockIdx.x >> 6;
    const int w = tid >> 5, lane = tid & 31;
    const int ta = w >> 1, mh = w & 1;

    // load 4 W tiles (global tile idx = bn*4 + ta)
    {
        const float4* src = (const float4*)(g_WpkI + (size_t)(bn * 4) * 8192);
        float4* dst = (float4*)sA;
        for (int p = tid; p < 8192; p += 256) dst[p] = __ldg(src + p);
    }
    if (tid < 64) {
        int np = bn * 64 + tid;
        sBias[tid] = g_bias[np >> 10][np & 1023];
    }

    const int v1 = tid + 256;
    const int b0s = tid >> 4, kq0 = (tid & 15) * 4;
    const int b1s = v1 >> 4,  kq1 = (v1 & 15) * 4;
    const int brow0 = (mh * 16 + (lane >> 2)) * 68 + (lane & 3);
    const int brow1 = (mh * 16 + 8 + (lane >> 2)) * 68 + (lane & 3);

    const float* tilebase = sA + ta * 8192;
    const int gate = (bn * 64) >> 10;
    const int nbase = (bn * 64) & 1023;
    __syncthreads();

    for (int mc = 0; mc < 256; mc++) {
        const int m0 = bm * 8192 + mc * 32;

        float acc[2][4];
#pragma unroll
        for (int g = 0; g < 2; g++)
#pragma unroll
            for (int j = 0; j < 4; j++) acc[g][j] = 0.f;

        float4 px0 = __ldg((const float4*)(X + (size_t)(m0 + b0s) * II + kq0));
        float4 px1 = __ldg((const float4*)(X + (size_t)(m0 + b1s) * II + kq1));

        for (int j = 0; j < 8; j++) {
            float* xb = sX + (j & 1) * 2176;
            __syncthreads();
            st4tf(xb + b0s * 68 + kq0, px0);
            st4tf(xb + b1s * 68 + kq1, px1);
            __syncthreads();
            if (j < 7) {
                int k1 = (j + 1) * 64;
                px0 = __ldg((const float4*)(X + (size_t)(m0 + b0s) * II + k1 + kq0));
                px1 = __ldg((const float4*)(X + (size_t)(m0 + b1s) * II + k1 + kq1));
            }
#pragma unroll
            for (int kt = 0; kt < 8; kt++) {
                const int colo = kt * 8;
                unsigned x0a = *(const unsigned*)(xb + brow0 + colo);
                unsigned x1a = *(const unsigned*)(xb + brow0 + colo + 4);
                unsigned x0b = *(const unsigned*)(xb + brow1 + colo);
                unsigned x1b = *(const unsigned*)(xb + brow1 + colo + 4);
                uint4 a = *(const uint4*)(tilebase + (j * 8 + kt) * 128 + lane * 4);
                mma_tf32(acc[0], a, x0a, x1a);
                mma_tf32(acc[1], a, x0b, x1b);
            }
        }

        // transpose through smem for coalesced stores
        __syncthreads();
#pragma unroll
        for (int g = 0; g < 2; g++)
#pragma unroll
            for (int j = 0; j < 4; j++) {
                int nrow = ta * 16 + (lane >> 2) + 8 * (j >> 1);
                int mcol = mh * 16 + g * 8 + 2 * (lane & 3) + (j & 1);
                sT[mcol * 68 + nrow] = acc[g][j];
            }
        __syncthreads();
#pragma unroll
        for (int e = 0; e < 2; e++) {
            int idx = tid + e * 256;
            int row = idx >> 4, q = idx & 15;
            float4 v = *(float4*)(sT + row * 68 + q * 4);
            v.x += sBias[q * 4 + 0]; v.y += sBias[q * 4 + 1];
            v.z += sBias[q * 4 + 2]; v.w += sBias[q * 4 + 3];
            *(float4*)(g_P + (size_t)gate * TBH + (size_t)(m0 + row) * HH + nbase + q * 4) = v;
        }
    }
}

// persistent tf32 recurrence
#define SMEM_FLOATS (49152 + 8704)
extern "C" __global__ void __launch_bounds__(256) lstm_kernel(float* __restrict__ out)
{
    extern __shared__ float smem[];
    float* sW  = smem;
    float* sB  = smem + 49152;
    float* sBh = sB;
    float* sBc = sB + 2 * 2176;

    const int tid = threadIdx.x, bId = blockIdx.x;
    const int w = tid >> 5, lane = tid & 31;
    const int kw = w >> 1, bgset = w & 1;

    const int s0 = 3 * bId;
    const int mats[3] = { s0 >> 6, (s0 + 1) >> 6, (s0 + 2) >> 6 };
    const bool uC0 = mats[0] >= 4, uC1 = mats[1] >= 4, uC2 = mats[2] >= 4;
    const bool needH = !(uC0 && uC1 && uC2);   // true for bId 0..85 (86 blocks)
    const bool needC = uC0 || uC1 || uC2;

#pragma unroll
    for (int tt = 0; tt < 3; tt++) {
        const float4* src = (const float4*)(g_Wpk + (size_t)(s0 + tt) * 16384);
        float4* dst = (float4*)(sW + tt * 16384);
        for (int p = tid; p < 4096; p += 256) dst[p] = __ldg(src + p);
    }

    const int v1 = tid + 256;
    const int b0s = tid >> 4, kq0 = (tid & 15) * 4;
    const int b1s = v1 >> 4,  kq1 = (v1 & 15) * 4;
    const int brow0 = (bgset * 16 + (lane >> 2)) * 68 + (lane & 3);
    const int brow1 = (bgset * 16 + 8 + (lane >> 2)) * 68 + (lane & 3);

    unsigned barM = 0;
    __syncthreads();

    for (int t = 0; t < TT; t++) {
        const int cur = t & 1, nxt = cur ^ 1;
        const float* c_in = g_c[cur];

        // ---------- phase 1 ----------
        float acc[3][2][4];
#pragma unroll
        for (int a = 0; a < 3; a++)
#pragma unroll
            for (int g = 0; g < 2; g++)
#pragma unroll
                for (int j = 0; j < 4; j++) acc[a][g][j] = 0.f;

        float4 ph0, ph1, pc0, pc1;
        if (needH) {
            ph0 = __ldcg((const float4*)(g_h + b0s * HH + kq0));
            ph1 = __ldcg((const float4*)(g_h + b1s * HH + kq1));
        }
        if (needC) {
            pc0 = __ldcg((const float4*)(c_in + b0s * HH + kq0));
            pc1 = __ldcg((const float4*)(c_in + b1s * HH + kq1));
        }

        for (int j = 0; j < 16; j++) {
            float* bh = sBh + (j & 1) * 2176;
            float* bc = sBc + (j & 1) * 2176;
            __syncthreads();
            if (needH) { st4tf(bh + b0s * 68 + kq0, ph0); st4tf(bh + b1s * 68 + kq1, ph1); }
            if (needC) { st4tf(bc + b0s * 68 + kq0, pc0); st4tf(bc + b1s * 68 + kq1, pc1); }
            __syncthreads();
            if (j < 15) {
                int k1 = (j + 1) * 64;
                if (needH) {
                    ph0 = __ldcg((const float4*)(g_h + b0s * HH + k1 + kq0));
                    ph1 = __ldcg((const float4*)(g_h + b1s * HH + k1 + kq1));
                }
                if (needC) {
                    pc0 = __ldcg((const float4*)(c_in + b0s * HH + k1 + kq0));
                    pc1 = __ldcg((const float4*)(c_in + b1s * HH + k1 + kq1));
                }
            }
#pragma unroll
            for (int q = 0; q < 2; q++) {
                const int kt = kw * 2 + q, colo = kt * 8;
                unsigned h0a = 0, h1a = 0, h0b = 0, h1b = 0;
                unsigned c0a = 0, c1a = 0, c0b = 0, c1b = 0;
                if (needH) {
                    h0a = *(const unsigned*)(bh + brow0 + colo);
                    h1a = *(const unsigned*)(bh + brow0 + colo + 4);
                    h0b = *(const unsigned*)(bh + brow1 + colo);
                    h1b = *(const unsigned*)(bh + brow1 + colo + 4);
                }
                if (needC) {
                    c0a = *(const unsigned*)(bc + brow0 + colo);
                    c1a = *(const unsigned*)(bc + brow0 + colo + 4);
                    c0b = *(const unsigned*)(bc + brow1 + colo);
                    c1b = *(const unsigned*)(bc + brow1 + colo + 4);
                }
                const int gkt = j * 8 + kt;
                uint4 a0 = *(const uint4*)(sW + gkt * 128 + lane * 4);
                uint4 a1 = *(const uint4*)(sW + 16384 + gkt * 128 + lane * 4);
                uint4 a2 = *(const uint4*)(sW + 32768 + gkt * 128 + lane * 4);
                mma_tf32(acc[0][0], a0, uC0 ? c0a : h0a, uC0 ? c1a : h1a);
                mma_tf32(acc[0][1], a0, uC0 ? c0b : h0b, uC0 ? c1b : h1b);
                mma_tf32(acc[1][0], a1, uC1 ? c0a : h0a, uC1 ? c1a : h1a);
                mma_tf32(acc[1][1], a1, uC1 ? c0b : h0b, uC1 ? c1b : h1b);
                mma_tf32(acc[2][0], a2, uC2 ? c0a : h0a, uC2 ? c1a : h1a);
                mma_tf32(acc[2][1], a2, uC2 ? c0b : h0b, uC2 ? c1b : h1b);
            }
        }

        __syncthreads();
        if (kw > 0) {
            float* dst = sB + (((kw - 1) * 2 + bgset) * 32 + lane) * 24;
#pragma unroll
            for (int a = 0; a < 3; a++)
#pragma unroll
                for (int g = 0; g < 2; g++)
#pragma unroll
                    for (int j = 0; j < 4; j++) dst[a * 8 + g * 4 + j] = acc[a][g][j];
        }
        __syncthreads();
        if (kw == 0) {
#pragma unroll
            for (int r = 0; r < 3; r++) {
                const float* sp = sB + ((r * 2 + bgset) * 32 + lane) * 24;
#pragma unroll
                for (int a = 0; a < 3; a++)
#pragma unroll
                    for (int g = 0; g < 2; g++)
#pragma unroll
                        for (int j = 0; j < 4; j++) acc[a][g][j] += sp[a * 8 + g * 4 + j];
            }
#pragma unroll
            for (int a = 0; a < 3; a++) {
                const int mat = (s0 + a) >> 6, ng = (s0 + a) & 63;
#pragma unroll
                for (int g = 0; g < 2; g++)
#pragma unroll
                    for (int j = 0; j < 4; j++) {
                        int row = ng * 16 + (lane >> 2) + 8 * (j >> 1);
                        int bcol = bgset * 16 + g * 8 + 2 * (lane & 3) + (j & 1);
                        g_acc[((mat << 10) + row) * 32 + bcol] = acc[a][g][j];
                    }
            }
        }
        gbarM(++barM);

        // ---------- pointwise ----------
        {
            int idx = bId * 256 + tid;
            int n = idx >> 5, b = idx & 31;
            int off = b * HH + n;
            size_t pb = (size_t)t * BH + off;
            float hi = __ldcg(&g_acc[n * 32 + b]);
            float hf = __ldcg(&g_acc[(1024 + n) * 32 + b]);
            float hc = __ldcg(&g_acc[(2048 + n) * 32 + b]);
            float ho = __ldcg(&g_acc[(3072 + n) * 32 + b]);
            float ci = __ldcg(&g_acc[(4096 + n) * 32 + b]);
            float cf = __ldcg(&g_acc[(5120 + n) * 32 + b]);
            float cold = __ldcg(&g_c[cur][off]);
            float pi = __ldg(&g_P[pb]) + hi + ci;
            float pf = __ldg(&g_P[(size_t)TBH + pb]) + hf + cf;
            float pg = __ldg(&g_P[2 * (size_t)TBH + pb]) + hc;
            float po = __ldg(&g_P[3 * (size_t)TBH + pb]) + ho;
            float iv = 1.f / (1.f + expf(-pi));
            float fv = 1.f / (1.f + expf(-pf));
            float gv = tanhf(pg);
            float cy = fmaf(fv, cold, iv * gv);
            g_c[nxt][off] = cy;
            g_po[off] = po;
        }
        gbarM(++barM);

        // ---------- phase 2 (blocks 0..63) ----------
        if (bId < 64) {
            float acc2[2][4];
#pragma unroll
            for (int g = 0; g < 2; g++)
#pragma unroll
                for (int j = 0; j < 4; j++) acc2[g][j] = 0.f;

            float* sCy = sBh;
            float* sA2 = sBc;
            const float* cyp = g_c[nxt];
            const float* wsrc = g_Wpk + (size_t)(384 + bId) * 16384;

            float4 py0 = __ldcg((const float4*)(cyp + b0s * HH + kq0));
            float4 py1 = __ldcg((const float4*)(cyp + b1s * HH + kq1));
            float4 pa  = __ldg((const float4*)(wsrc) + tid);

            for (int j = 0; j < 16; j++) {
                float* cb = sCy + (j & 1) * 2176;
                float* ab = sA2 + (j & 1) * 1088;
                __syncthreads();
                st4tf(cb + b0s * 68 + kq0, py0);
                st4tf(cb + b1s * 68 + kq1, py1);
                *(float4*)(ab + tid * 4) = pa;
                __syncthreads();
                if (j < 15) {
                    int k1 = (j + 1) * 64;
                    py0 = __ldcg((const float4*)(cyp + b0s * HH + k1 + kq0));
                    py1 = __ldcg((const float4*)(cyp + b1s * HH + k1 + kq1));
                    pa  = __ldg((const float4*)(wsrc + (j + 1) * 1024) + tid);
                }
#pragma unroll
                for (int q = 0; q < 2; q++) {
                    const int kt = kw * 2 + q, colo = kt * 8;
                    unsigned y0a = *(const unsigned*)(cb + brow0 + colo);
                    unsigned y1a = *(const unsigned*)(cb + brow0 + colo + 4);
                    unsigned y0b = *(const unsigned*)(cb + brow1 + colo);
                    unsigned y1b = *(const unsigned*)(cb + brow1 + colo + 4);
                    uint4 af = *(const uint4*)(ab + kt * 128 + lane * 4);
                    mma_tf32(acc2[0], af, y0a, y1a);
                    mma_tf32(acc2[1], af, y0b, y1b);
                }
            }

            __syncthreads();
            if (kw > 0) {
                float* dst = sCy + (((kw - 1) * 2 + bgset) * 32 + lane) * 8;
#pragma unroll
                for (int g = 0; g < 2; g++)
#pragma unroll
                    for (int j = 0; j < 4; j++) dst[g * 4 + j] = acc2[g][j];
            }
            __syncthreads();
            if (kw == 0) {
#pragma unroll
                for (int r = 0; r < 3; r++) {
                    const float* sp = sCy + ((r * 2 + bgset) * 32 + lane) * 8;
#pragma unroll
                    for (int g = 0; g < 2; g++)
#pragma unroll
                        for (int j = 0; j < 4; j++) acc2[g][j] += sp[g * 4 + j];
                }
#pragma unroll
                for (int g = 0; g < 2; g++)
#pragma unroll
                    for (int j = 0; j < 4; j++) {
                        int row = bId * 16 + (lane >> 2) + 8 * (j >> 1);
                        int bcol = bgset * 16 + g * 8 + 2 * (lane & 3) + (j & 1);
                        int off = bcol * HH + row;
                        float po = __ldcg(&g_po[off]);
                        float cyv = __ldcg(&g_c[nxt][off]);
                        float o = 1.f / (1.f + expf(-(po + acc2[g][j])));
                        float hy = o * tanhf(cyv);
                        g_h[off] = hy;
                        out[(size_t)t * BH + off] = hy;
                    }
            }
        }
        // only h-readers (blocks 0..85) synchronize on h; C-only blocks run ahead
        if (needH) gbar3((unsigned)(t + 1));
    }
}

extern "C" void kernel_launch(void* const* d_in, const int* in_sizes, int n_in,
                              void* d_out, int out_size)
{
    const float* X     = (const float*)d_in[0];
    const float* h0    = (const float*)d_in[1];
    const float* c0    = (const float*)d_in[2];
    const float* w_ii  = (const float*)d_in[3];
    const float* w_hi  = (const float*)d_in[4];
    const float* w_ci  = (const float*)d_in[5];
    const float* w_if  = (const float*)d_in[6];
    const float* w_hf  = (const float*)d_in[7];
    const float* w_cf  = (const float*)d_in[8];
    const float* w_ic  = (const float*)d_in[9];
    const float* w_hc  = (const float*)d_in[10];
    const float* w_io  = (const float*)d_in[11];
    const float* w_ho  = (const float*)d_in[12];
    const float* w_cyo = (const float*)d_in[13];
    float* out = (float*)d_out;

    cudaFuncSetAttribute(lstm_kernel,
                         cudaFuncAttributeMaxDynamicSharedMemorySize,
                         SMEM_FLOATS * 4);
    cudaFuncSetAttribute(proj2_kernel,
                         cudaFuncAttributeMaxDynamicSharedMemorySize,
                         PROJ_SMEM * 4);

    init_kernel<<<128, 256>>>(h0, c0,
        (const float*)d_in[14], (const float*)d_in[15], (const float*)d_in[16],
        (const float*)d_in[17], (const float*)d_in[18], (const float*)d_in[19],
        (const float*)d_in[20], (const float*)d_in[21], (const float*)d_in[22],
        (const float*)d_in[23], (const float*)d_in[24]);
    pack_kernel<<<28672, 256>>>(w_hi, w_hf, w_hc, w_ho, w_ci, w_cf, w_cyo);
    pack_in_kernel<<<8192, 256>>>(w_ii, w_if, w_ic, w_io);
    proj2_kernel<<<128, 256, PROJ_SMEM * 4>>>(X);
    lstm_kernel<<<NBLK, 256, SMEM_FLOATS * 4>>>(out);
}